// round 1
// baseline (speedup 1.0000x reference)
#include <cuda_runtime.h>
#include <cuda_bf16.h>
#include <math.h>

// Problem constants
#define BB   32
#define LL   4096
#define CC   512
#define WSZ  64
#define SHIFT 32
#define NH   8
#define DK   64
#define HID  2048
#define NW   64                 // windows per batch = LL/WSZ
#define TOK  (BB*LL)            // 131072 tokens
#define Y_ELEMS   ((size_t)TOK*CC)          // 67108864
#define ATTN_ELEMS ((size_t)BB*NW*NH*WSZ*WSZ) // 67108864

// ---------------- scratch (device globals; no allocation allowed) -------------
__device__ float g_h  [(size_t)TOK*CC];   // LN1(rolled) output; later reused as LN2 output
__device__ float g_q  [(size_t)TOK*CC];   // q; later reused as y1 (attn branch output + residual)
__device__ float g_k  [(size_t)TOK*CC];
__device__ float g_v  [(size_t)TOK*CC];
__device__ float g_ctx[(size_t)TOK*CC];
__device__ float g_f  [(size_t)TOK*HID];  // FFN hidden (post GELU)
__device__ float g_f2 [(size_t)TOK*HID];  // FFN hidden after dwconv+GELU

__device__ __forceinline__ float gelu_f(float x) {
    return 0.5f * x * (1.0f + erff(x * 0.70710678118654752440f));
}

// ---------------- LayerNorm (+ optional roll of source index) ----------------
// out[row] = LN(x[src_row]) ; src_row = (b, (l+SHIFT)%L) when rolled, else row.
__global__ void __launch_bounds__(128) ln_kernel(
    const float* __restrict__ x, float* __restrict__ out,
    const float* __restrict__ g, const float* __restrict__ b, int rolled)
{
    int row = blockIdx.x;                       // destination row
    int bt  = row >> 12;                        // L = 4096 = 2^12
    int l   = row & (LL - 1);
    int src = rolled ? ((bt << 12) | ((l + SHIFT) & (LL - 1))) : row;
    const float* xr = x + (size_t)src * CC;

    int t = threadIdx.x;                        // 128 threads, 4 floats each
    float4 v = *(const float4*)(xr + t * 4);
    float s  = v.x + v.y + v.z + v.w;
    float ss = v.x*v.x + v.y*v.y + v.z*v.z + v.w*v.w;
    #pragma unroll
    for (int o = 16; o > 0; o >>= 1) {
        s  += __shfl_xor_sync(0xffffffffu, s,  o);
        ss += __shfl_xor_sync(0xffffffffu, ss, o);
    }
    __shared__ float red[8];
    int wid = t >> 5, lid = t & 31;
    if (lid == 0) { red[wid] = s; red[4 + wid] = ss; }
    __syncthreads();
    s  = red[0] + red[1] + red[2] + red[3];
    ss = red[4] + red[5] + red[6] + red[7];

    float mean = s * (1.0f / CC);
    float var  = ss * (1.0f / CC) - mean * mean;
    float rstd = rsqrtf(var + 1e-5f);

    float4 gg = *(const float4*)(g + t * 4);
    float4 bb4 = *(const float4*)(b + t * 4);
    float4 o4;
    o4.x = (v.x - mean) * rstd * gg.x + bb4.x;
    o4.y = (v.y - mean) * rstd * gg.y + bb4.y;
    o4.z = (v.z - mean) * rstd * gg.z + bb4.z;
    o4.w = (v.w - mean) * rstd * gg.w + bb4.w;
    *(float4*)(out + (size_t)row * CC + t * 4) = o4;
}

// ---------------- fp32 NT SGEMM: C[M,N] = A[M,K] @ B[N,K]^T + epilogue -------
// MODE 0: plain store
// MODE 1: o-proj: dest row remapped by +SHIFT roll, add x (residual) -> y1
// MODE 2: + bias, GELU (c1)
// MODE 3: + bias + addsrc (y1 residual) (c3, final y)
template<int MODE>
__global__ void __launch_bounds__(256) sgemm_nt(
    const float* __restrict__ A, const float* __restrict__ Bw,
    float* __restrict__ Cc, int M, int N, int K,
    const float* __restrict__ bias, const float* __restrict__ addsrc)
{
    __shared__ float As[16][128];
    __shared__ float Bs[16][128];
    const int tid = threadIdx.x;
    const int bm = blockIdx.y * 128;
    const int bn = blockIdx.x * 128;
    const int tx = tid & 15, ty = tid >> 4;

    float acc[8][8];
    #pragma unroll
    for (int i = 0; i < 8; i++)
        #pragma unroll
        for (int j = 0; j < 8; j++) acc[i][j] = 0.0f;

    const int arow0 = tid >> 2;          // 0..63
    const int acol  = (tid & 3) * 4;     // 0,4,8,12

    for (int k0 = 0; k0 < K; k0 += 16) {
        #pragma unroll
        for (int r = 0; r < 2; r++) {
            int row = arow0 + r * 64;
            float4 a4 = *(const float4*)(A  + (size_t)(bm + row) * K + k0 + acol);
            As[acol + 0][row] = a4.x; As[acol + 1][row] = a4.y;
            As[acol + 2][row] = a4.z; As[acol + 3][row] = a4.w;
            float4 b4 = *(const float4*)(Bw + (size_t)(bn + row) * K + k0 + acol);
            Bs[acol + 0][row] = b4.x; Bs[acol + 1][row] = b4.y;
            Bs[acol + 2][row] = b4.z; Bs[acol + 3][row] = b4.w;
        }
        __syncthreads();
        #pragma unroll
        for (int kk = 0; kk < 16; kk++) {
            float ra[8], rb[8];
            #pragma unroll
            for (int i = 0; i < 8; i++) ra[i] = As[kk][ty * 8 + i];
            #pragma unroll
            for (int j = 0; j < 8; j++) rb[j] = Bs[kk][tx * 8 + j];
            #pragma unroll
            for (int i = 0; i < 8; i++)
                #pragma unroll
                for (int j = 0; j < 8; j++)
                    acc[i][j] += ra[i] * rb[j];
        }
        __syncthreads();
    }

    #pragma unroll
    for (int i = 0; i < 8; i++) {
        int m = bm + ty * 8 + i;
        #pragma unroll
        for (int j = 0; j < 8; j++) {
            int n = bn + tx * 8 + j;
            float val = acc[i][j];
            if (MODE == 0) {
                Cc[(size_t)m * N + n] = val;
            } else if (MODE == 1) {
                int bt = m >> 12, l = m & (LL - 1);
                int ld = (l + SHIFT) & (LL - 1);
                size_t mrow = ((size_t)(bt << 12) | ld);
                val += addsrc[mrow * N + n];
                Cc[mrow * N + n] = val;
            } else if (MODE == 2) {
                val += bias[n];
                Cc[(size_t)m * N + n] = gelu_f(val);
            } else { // MODE 3
                val += bias[n] + addsrc[(size_t)m * N + n];
                Cc[(size_t)m * N + n] = val;
            }
        }
    }
}

// ---------------- window attention ------------------------------------------
// block = (head h, window w). 256 threads. q/k stored [d][t] in smem; v [t][d].
__global__ void __launch_bounds__(256) attn_kernel(
    const float* __restrict__ q, const float* __restrict__ k, const float* __restrict__ v,
    const float* __restrict__ rel_table,
    float* __restrict__ attn_out, float* __restrict__ ctx, int write_attn)
{
    __shared__ float sQ[64][64];   // [d][t]; reused as S^T [t2][t1] later
    __shared__ float sK[64][64];   // [d][t]
    __shared__ float sV[64][64];   // [t2][d]

    const int h = blockIdx.x;      // 0..7
    const int w = blockIdx.y;      // 0..2047
    const int tid = threadIdx.x;
    const int t  = tid >> 2;       // 0..63 (query row / load row)
    const int qd = tid & 3;        // 0..3  (16-wide column slice)

    const size_t base = (size_t)w * WSZ * CC + (size_t)h * DK;

    #pragma unroll
    for (int i = 0; i < 4; i++) {
        int d0 = qd * 16 + i * 4;
        float4 qv = *(const float4*)(q + base + (size_t)t * CC + d0);
        sQ[d0 + 0][t] = qv.x; sQ[d0 + 1][t] = qv.y;
        sQ[d0 + 2][t] = qv.z; sQ[d0 + 3][t] = qv.w;
        float4 kv = *(const float4*)(k + base + (size_t)t * CC + d0);
        sK[d0 + 0][t] = kv.x; sK[d0 + 1][t] = kv.y;
        sK[d0 + 2][t] = kv.z; sK[d0 + 3][t] = kv.w;
        float4 vv = *(const float4*)(v + base + (size_t)t * CC + d0);
        *(float4*)(&sV[t][d0]) = vv;
    }
    __syncthreads();

    // scores: this thread owns row t, cols t2 = qd*16 + j
    float sc[16];
    #pragma unroll
    for (int j = 0; j < 16; j++) sc[j] = 0.0f;
    #pragma unroll
    for (int d = 0; d < 64; d++) {
        float qv = sQ[d][t];
        #pragma unroll
        for (int j = 0; j < 16; j++)
            sc[j] += qv * sK[d][qd * 16 + j];
    }

    const bool last = ((w & (NW - 1)) == (NW - 1));
    #pragma unroll
    for (int j = 0; j < 16; j++) {
        int t2 = qd * 16 + j;
        float bia = rel_table[(t - t2 + WSZ - 1) * NH + h];
        float s = sc[j] * 0.125f + bia;
        if (last && ((t < 32) != (t2 < 32))) s -= 100.0f;
        sc[j] = s;
    }

    // softmax across the 4-thread group (lanes 4t..4t+3 are in the same warp)
    float mx = sc[0];
    #pragma unroll
    for (int j = 1; j < 16; j++) mx = fmaxf(mx, sc[j]);
    mx = fmaxf(mx, __shfl_xor_sync(0xffffffffu, mx, 1));
    mx = fmaxf(mx, __shfl_xor_sync(0xffffffffu, mx, 2));
    float sum = 0.0f;
    #pragma unroll
    for (int j = 0; j < 16; j++) { sc[j] = __expf(sc[j] - mx); sum += sc[j]; }
    sum += __shfl_xor_sync(0xffffffffu, sum, 1);
    sum += __shfl_xor_sync(0xffffffffu, sum, 2);
    float inv = 1.0f / sum;
    #pragma unroll
    for (int j = 0; j < 16; j++) sc[j] *= inv;

    if (write_attn) {
        size_t ao = ((((size_t)w * NH + h) * WSZ) + t) * WSZ + qd * 16;
        #pragma unroll
        for (int j4 = 0; j4 < 4; j4++) {
            float4 o4 = make_float4(sc[j4*4+0], sc[j4*4+1], sc[j4*4+2], sc[j4*4+3]);
            *(float4*)(attn_out + ao + j4 * 4) = o4;
        }
    }

    __syncthreads();                       // all done reading sQ/sK
    #pragma unroll
    for (int j = 0; j < 16; j++)
        sQ[qd * 16 + j][t] = sc[j];        // S^T: [t2][t1]
    __syncthreads();

    // ctx[t, d] = sum_t2 S[t][t2] * V[t2][d]; this thread: row t, d = qd*16+j
    float oacc[16];
    #pragma unroll
    for (int j = 0; j < 16; j++) oacc[j] = 0.0f;
    #pragma unroll
    for (int t2 = 0; t2 < 64; t2++) {
        float sv = sQ[t2][t];
        #pragma unroll
        for (int j = 0; j < 16; j++)
            oacc[j] += sv * sV[t2][qd * 16 + j];
    }
    size_t co = base + (size_t)t * CC + qd * 16;
    #pragma unroll
    for (int j4 = 0; j4 < 4; j4++) {
        float4 o4 = make_float4(oacc[j4*4+0], oacc[j4*4+1], oacc[j4*4+2], oacc[j4*4+3]);
        *(float4*)(ctx + co + j4 * 4) = o4;
    }
}

// ---------------- depthwise conv along L (k=3, zero pad) + GELU --------------
__global__ void __launch_bounds__(256) dwconv_kernel(
    const float* __restrict__ f, const float* __restrict__ c2w,
    const float* __restrict__ c2b, float* __restrict__ out)
{
    size_t idx = (size_t)blockIdx.x * blockDim.x + threadIdx.x;   // over TOK*HID/4
    if (idx >= (size_t)TOK * HID / 4) return;
    size_t e = idx * 4;
    int ch = (int)(e % HID);
    size_t row = e / HID;
    int l = (int)(row & (LL - 1));

    float4 fc = *(const float4*)(f + e);
    float4 fm = make_float4(0.f, 0.f, 0.f, 0.f);
    float4 fp = make_float4(0.f, 0.f, 0.f, 0.f);
    if (l > 0)      fm = *(const float4*)(f + e - HID);
    if (l < LL - 1) fp = *(const float4*)(f + e + HID);

    float r[4];
    float fmv[4] = {fm.x, fm.y, fm.z, fm.w};
    float fcv[4] = {fc.x, fc.y, fc.z, fc.w};
    float fpv[4] = {fp.x, fp.y, fp.z, fp.w};
    #pragma unroll
    for (int j = 0; j < 4; j++) {
        int c = ch + j;
        float w0 = c2w[c * 3 + 0], w1 = c2w[c * 3 + 1], w2 = c2w[c * 3 + 2];
        float dw = fmv[j] * w0 + fcv[j] * w1 + fpv[j] * w2 + c2b[c];
        r[j] = gelu_f(dw + fcv[j]);
    }
    *(float4*)(out + e) = make_float4(r[0], r[1], r[2], r[3]);
}

// ---------------- launch ------------------------------------------------------
extern "C" void kernel_launch(void* const* d_in, const int* in_sizes, int n_in,
                              void* d_out, int out_size)
{
    const float* x      = (const float*)d_in[0];
    const float* ln1_g  = (const float*)d_in[1];
    const float* ln1_b  = (const float*)d_in[2];
    const float* w_q    = (const float*)d_in[3];
    const float* w_k    = (const float*)d_in[4];
    const float* w_v    = (const float*)d_in[5];
    const float* w_o    = (const float*)d_in[6];
    const float* rel    = (const float*)d_in[7];
    const float* ln2_g  = (const float*)d_in[8];
    const float* ln2_b  = (const float*)d_in[9];
    const float* c1_w   = (const float*)d_in[10];
    const float* c1_b   = (const float*)d_in[11];
    const float* c2_w   = (const float*)d_in[12];
    const float* c2_b   = (const float*)d_in[13];
    const float* c3_w   = (const float*)d_in[14];
    const float* c3_b   = (const float*)d_in[15];
    float* out = (float*)d_out;

    float *h, *q, *k, *v, *ctx, *f, *f2;
    cudaGetSymbolAddress((void**)&h,   g_h);
    cudaGetSymbolAddress((void**)&q,   g_q);
    cudaGetSymbolAddress((void**)&k,   g_k);
    cudaGetSymbolAddress((void**)&v,   g_v);
    cudaGetSymbolAddress((void**)&ctx, g_ctx);
    cudaGetSymbolAddress((void**)&f,   g_f);
    cudaGetSymbolAddress((void**)&f2,  g_f2);
    float* y1  = q;   // reuse: q dead after attention
    float* fln = h;   // reuse: h dead after qkv GEMMs

    const int write_attn = ((size_t)out_size >= Y_ELEMS + ATTN_ELEMS) ? 1 : 0;
    float* attn_out = out + Y_ELEMS;

    // 1. LN1 + roll(-SHIFT)
    ln_kernel<<<TOK, 128>>>(x, h, ln1_g, ln1_b, 1);

    // 2. q/k/v projections
    dim3 g512(CC / 128, TOK / 128);      // (4, 1024)
    sgemm_nt<0><<<g512, 256>>>(h, w_q, q, TOK, CC, CC, nullptr, nullptr);
    sgemm_nt<0><<<g512, 256>>>(h, w_k, k, TOK, CC, CC, nullptr, nullptr);
    sgemm_nt<0><<<g512, 256>>>(h, w_v, v, TOK, CC, CC, nullptr, nullptr);

    // 3. windowed attention (writes attn probs to d_out tail, ctx token-major)
    dim3 ga(NH, BB * NW);                // (8, 2048)
    attn_kernel<<<ga, 256>>>(q, k, v, rel, attn_out, ctx, write_attn);

    // 4. o-proj + roll(+SHIFT) + residual -> y1
    sgemm_nt<1><<<g512, 256>>>(ctx, w_o, y1, TOK, CC, CC, nullptr, x);

    // 5. LN2
    ln_kernel<<<TOK, 128>>>(y1, fln, ln2_g, ln2_b, 0);

    // 6. c1 + bias + GELU
    dim3 g2048(HID / 128, TOK / 128);    // (16, 1024)
    sgemm_nt<2><<<g2048, 256>>>(fln, c1_w, f, TOK, HID, CC, c1_b, nullptr);

    // 7. depthwise conv (k=3) + bias + residual-in-FFN + GELU
    size_t nthread = (size_t)TOK * HID / 4;
    dwconv_kernel<<<(unsigned)((nthread + 255) / 256), 256>>>(f, c2_w, c2_b, f2);

    // 8. c3 + bias + residual -> final y
    sgemm_nt<3><<<g512, 256>>>(f2, c3_w, out, TOK, CC, HID, c3_b, y1);
}

// round 3
// speedup vs baseline: 1.8257x; 1.8257x over previous
#include <cuda_runtime.h>
#include <cuda_bf16.h>
#include <math.h>
#include <stdint.h>

// Problem constants
#define BB   32
#define LL   4096
#define CC   512
#define WSZ  64
#define SHIFT 32
#define NH   8
#define DK   64
#define HID  2048
#define NW   64                 // windows per batch = LL/WS
#define TOK  (BB*LL)            // 131072 tokens
#define Y_ELEMS   ((size_t)TOK*CC)
#define ATTN_ELEMS ((size_t)BB*NW*NH*WSZ*WSZ)

// ---------------- scratch (device globals; no allocation allowed) -------------
__device__ float g_h  [(size_t)TOK*CC];
__device__ float g_q  [(size_t)TOK*CC];
__device__ float g_k  [(size_t)TOK*CC];
__device__ float g_v  [(size_t)TOK*CC];
__device__ float g_ctx[(size_t)TOK*CC];
__device__ float g_f  [(size_t)TOK*HID];
__device__ float g_f2 [(size_t)TOK*HID];

__device__ __forceinline__ float gelu_f(float x) {
    return 0.5f * x * (1.0f + erff(x * 0.70710678118654752440f));
}

// ---------------- LayerNorm (+ optional roll of source index) ----------------
__global__ void __launch_bounds__(128) ln_kernel(
    const float* __restrict__ x, float* __restrict__ out,
    const float* __restrict__ g, const float* __restrict__ b, int rolled)
{
    int row = blockIdx.x;
    int bt  = row >> 12;
    int l   = row & (LL - 1);
    int src = rolled ? ((bt << 12) | ((l + SHIFT) & (LL - 1))) : row;
    const float* xr = x + (size_t)src * CC;

    int t = threadIdx.x;
    float4 v = *(const float4*)(xr + t * 4);
    float s  = v.x + v.y + v.z + v.w;
    float ss = v.x*v.x + v.y*v.y + v.z*v.z + v.w*v.w;
    #pragma unroll
    for (int o = 16; o > 0; o >>= 1) {
        s  += __shfl_xor_sync(0xffffffffu, s,  o);
        ss += __shfl_xor_sync(0xffffffffu, ss, o);
    }
    __shared__ float red[8];
    int wid = t >> 5, lid = t & 31;
    if (lid == 0) { red[wid] = s; red[4 + wid] = ss; }
    __syncthreads();
    s  = red[0] + red[1] + red[2] + red[3];
    ss = red[4] + red[5] + red[6] + red[7];

    float mean = s * (1.0f / CC);
    float var  = ss * (1.0f / CC) - mean * mean;
    float rstd = rsqrtf(var + 1e-5f);

    float4 gg = *(const float4*)(g + t * 4);
    float4 bb4 = *(const float4*)(b + t * 4);
    float4 o4;
    o4.x = (v.x - mean) * rstd * gg.x + bb4.x;
    o4.y = (v.y - mean) * rstd * gg.y + bb4.y;
    o4.z = (v.z - mean) * rstd * gg.z + bb4.z;
    o4.w = (v.w - mean) * rstd * gg.w + bb4.w;
    *(float4*)(out + (size_t)row * CC + t * 4) = o4;
}

// ---------------- bf16x3 split-precision tensor-core GEMM --------------------
// C[M,N] = A[M,K] @ B[N,K]^T  with fp32-equivalent accuracy:
//   x = hi(x) + lo(x) in bf16;  acc += Ah*Bh + Ah*Bl + Al*Bh   (fp32 accum)
// MODE 0: plain   MODE 1: roll(+SHIFT) dest + residual
// MODE 2: +bias, GELU    MODE 3: +bias + addsrc
#define Bb16M 128
#define Bb16N 128
#define Bb16K 32

__device__ __forceinline__ uint32_t cvta_smem(const void* p) {
    return (uint32_t)__cvta_generic_to_shared(p);
}
__device__ __forceinline__ void ldsm4(uint32_t* r, uint32_t addr) {
    asm volatile("ldmatrix.sync.aligned.m8n8.x4.shared.b16 {%0,%1,%2,%3}, [%4];"
        : "=r"(r[0]), "=r"(r[1]), "=r"(r[2]), "=r"(r[3]) : "r"(addr));
}
__device__ __forceinline__ void ldsm2(uint32_t* r, uint32_t addr) {
    asm volatile("ldmatrix.sync.aligned.m8n8.x2.shared.b16 {%0,%1}, [%2];"
        : "=r"(r[0]), "=r"(r[1]) : "r"(addr));
}
__device__ __forceinline__ void mma16816(float* c, const uint32_t* a, const uint32_t* b) {
    asm volatile("mma.sync.aligned.m16n8k16.row.col.f32.bf16.bf16.f32 "
        "{%0,%1,%2,%3},{%4,%5,%6,%7},{%8,%9},{%0,%1,%2,%3};"
        : "+f"(c[0]), "+f"(c[1]), "+f"(c[2]), "+f"(c[3])
        : "r"(a[0]), "r"(a[1]), "r"(a[2]), "r"(a[3]), "r"(b[0]), "r"(b[1]));
}
// swizzled element offset within a [rows][32] bf16 tile (conflict-free ldmatrix)
__device__ __forceinline__ int swz(int r, int k) {
    return r * 32 + ((((k >> 3) ^ ((r >> 1) & 3)) & 3) << 3) + (k & 7);
}
__device__ __forceinline__ uint32_t pack_bf2(__nv_bfloat16 a, __nv_bfloat16 b) {
    return (uint32_t)__bfloat16_as_ushort(a) | ((uint32_t)__bfloat16_as_ushort(b) << 16);
}
__device__ __forceinline__ void split_store4(
    __nv_bfloat16* Hh, __nv_bfloat16* Ll, int off, float4 v)
{
    __nv_bfloat16 h0 = __float2bfloat16(v.x);
    __nv_bfloat16 h1 = __float2bfloat16(v.y);
    __nv_bfloat16 h2 = __float2bfloat16(v.z);
    __nv_bfloat16 h3 = __float2bfloat16(v.w);
    __nv_bfloat16 l0 = __float2bfloat16(v.x - __bfloat162float(h0));
    __nv_bfloat16 l1 = __float2bfloat16(v.y - __bfloat162float(h1));
    __nv_bfloat16 l2 = __float2bfloat16(v.z - __bfloat162float(h2));
    __nv_bfloat16 l3 = __float2bfloat16(v.w - __bfloat162float(h3));
    *(uint2*)(Hh + off) = make_uint2(pack_bf2(h0, h1), pack_bf2(h2, h3));
    *(uint2*)(Ll + off) = make_uint2(pack_bf2(l0, l1), pack_bf2(l2, l3));
}

template<int MODE>
__global__ void __launch_bounds__(256) mma_gemm(
    const float* __restrict__ A, const float* __restrict__ Bw,
    float* __restrict__ Cc, int M, int N, int K,
    const float* __restrict__ bias, const float* __restrict__ addsrc)
{
    __shared__ __nv_bfloat16 Ah[Bb16M * Bb16K];
    __shared__ __nv_bfloat16 Al[Bb16M * Bb16K];
    __shared__ __nv_bfloat16 Bh[Bb16N * Bb16K];
    __shared__ __nv_bfloat16 Bl[Bb16N * Bb16K];

    const int tid  = threadIdx.x;
    const int bm   = blockIdx.y * Bb16M;
    const int bn   = blockIdx.x * Bb16N;
    const int warp = tid >> 5, lane = tid & 31;
    const int wm = (warp & 1) * 64;      // 2 warps along M
    const int wn = (warp >> 1) * 32;     // 4 warps along N

    float acc[4][4][4];
    #pragma unroll
    for (int i = 0; i < 4; i++)
        #pragma unroll
        for (int j = 0; j < 4; j++)
            #pragma unroll
            for (int c = 0; c < 4; c++) acc[i][j][c] = 0.0f;

    // gmem tile loads: 128 rows x 32 cols fp32 each for A and B
    const int lr = tid >> 3;          // 0..31
    const int lc = (tid & 7) * 4;     // 0,4,...,28
    const float* Aptr = A  + (size_t)(bm + lr) * K + lc;
    const float* Bptr = Bw + (size_t)(bn + lr) * K + lc;

    float4 ra[4], rb[4];
    #pragma unroll
    for (int i = 0; i < 4; i++) {
        ra[i] = *(const float4*)(Aptr + (size_t)i * 32 * K);
        rb[i] = *(const float4*)(Bptr + (size_t)i * 32 * K);
    }

    const int nk = K / Bb16K;
    for (int kb = 0; kb < nk; kb++) {
        #pragma unroll
        for (int i = 0; i < 4; i++) {
            int r = lr + i * 32;
            int off = swz(r, lc);
            split_store4(Ah, Al, off, ra[i]);
            split_store4(Bh, Bl, off, rb[i]);
        }
        __syncthreads();

        if (kb + 1 < nk) {
            size_t ko = (size_t)(kb + 1) * Bb16K;
            #pragma unroll
            for (int i = 0; i < 4; i++) {
                ra[i] = *(const float4*)(Aptr + ko + (size_t)i * 32 * K);
                rb[i] = *(const float4*)(Bptr + ko + (size_t)i * 32 * K);
            }
        }

        #pragma unroll
        for (int kf = 0; kf < 2; kf++) {
            const int k0 = kf * 16;
            uint32_t fah[4][4], fal[4][4], fbh[4][2], fbl[4][2];

            const int arow = wm + (lane & 15);
            const int akc  = k0 + (lane >> 4) * 8;
            #pragma unroll
            for (int mi = 0; mi < 4; mi++) {
                int off = swz(arow + mi * 16, akc);
                ldsm4(fah[mi], cvta_smem(Ah + off));
                ldsm4(fal[mi], cvta_smem(Al + off));
            }
            const int brow = wn + (lane & 7);
            const int bkc  = k0 + ((lane >> 3) & 1) * 8;
            #pragma unroll
            for (int ni = 0; ni < 4; ni++) {
                int off = swz(brow + ni * 8, bkc);
                ldsm2(fbh[ni], cvta_smem(Bh + off));
                ldsm2(fbl[ni], cvta_smem(Bl + off));
            }
            #pragma unroll
            for (int mi = 0; mi < 4; mi++)
                #pragma unroll
                for (int ni = 0; ni < 4; ni++) {
                    mma16816(acc[mi][ni], fah[mi], fbh[ni]);
                    mma16816(acc[mi][ni], fah[mi], fbl[ni]);
                    mma16816(acc[mi][ni], fal[mi], fbh[ni]);
                }
        }
        __syncthreads();
    }

    // epilogue: thread owns (row = base + lane/4 [+8], cols = (lane%4)*2, +1)
    const int rbase = bm + wm + (lane >> 2);
    const int cbase = bn + wn + (lane & 3) * 2;
    #pragma unroll
    for (int mi = 0; mi < 4; mi++) {
        #pragma unroll
        for (int half = 0; half < 2; half++) {
            int m = rbase + mi * 16 + half * 8;
            #pragma unroll
            for (int ni = 0; ni < 4; ni++) {
                int n = cbase + ni * 8;
                float v0 = acc[mi][ni][half * 2 + 0];
                float v1 = acc[mi][ni][half * 2 + 1];
                if (MODE == 0) {
                    *(float2*)(Cc + (size_t)m * N + n) = make_float2(v0, v1);
                } else if (MODE == 1) {
                    int bt = m >> 12, l = m & (LL - 1);
                    int ld = (l + SHIFT) & (LL - 1);
                    size_t mrow = ((size_t)(bt << 12) | ld);
                    float2 r0 = *(const float2*)(addsrc + mrow * N + n);
                    *(float2*)(Cc + mrow * N + n) = make_float2(v0 + r0.x, v1 + r0.y);
                } else if (MODE == 2) {
                    float2 b2 = *(const float2*)(bias + n);
                    *(float2*)(Cc + (size_t)m * N + n) =
                        make_float2(gelu_f(v0 + b2.x), gelu_f(v1 + b2.y));
                } else {
                    float2 b2 = *(const float2*)(bias + n);
                    float2 r0 = *(const float2*)(addsrc + (size_t)m * N + n);
                    *(float2*)(Cc + (size_t)m * N + n) =
                        make_float2(v0 + b2.x + r0.x, v1 + b2.y + r0.y);
                }
            }
        }
    }
}

// ---------------- window attention (fp32 SIMT; small) ------------------------
__global__ void __launch_bounds__(256) attn_kernel(
    const float* __restrict__ q, const float* __restrict__ k, const float* __restrict__ v,
    const float* __restrict__ rel_table,
    float* __restrict__ attn_out, float* __restrict__ ctx, int write_attn)
{
    __shared__ float sQ[64][64];
    __shared__ float sK[64][64];
    __shared__ float sV[64][64];

    const int h = blockIdx.x;
    const int w = blockIdx.y;
    const int tid = threadIdx.x;
    const int t  = tid >> 2;
    const int qd = tid & 3;

    const size_t base = (size_t)w * WSZ * CC + (size_t)h * DK;

    #pragma unroll
    for (int i = 0; i < 4; i++) {
        int d0 = qd * 16 + i * 4;
        float4 qv = *(const float4*)(q + base + (size_t)t * CC + d0);
        sQ[d0 + 0][t] = qv.x; sQ[d0 + 1][t] = qv.y;
        sQ[d0 + 2][t] = qv.z; sQ[d0 + 3][t] = qv.w;
        float4 kv = *(const float4*)(k + base + (size_t)t * CC + d0);
        sK[d0 + 0][t] = kv.x; sK[d0 + 1][t] = kv.y;
        sK[d0 + 2][t] = kv.z; sK[d0 + 3][t] = kv.w;
        float4 vv = *(const float4*)(v + base + (size_t)t * CC + d0);
        *(float4*)(&sV[t][d0]) = vv;
    }
    __syncthreads();

    float sc[16];
    #pragma unroll
    for (int j = 0; j < 16; j++) sc[j] = 0.0f;
    #pragma unroll
    for (int d = 0; d < 64; d++) {
        float qv = sQ[d][t];
        #pragma unroll
        for (int j = 0; j < 16; j++)
            sc[j] += qv * sK[d][qd * 16 + j];
    }

    const bool last = ((w & (NW - 1)) == (NW - 1));
    #pragma unroll
    for (int j = 0; j < 16; j++) {
        int t2 = qd * 16 + j;
        float bia = rel_table[(t - t2 + WSZ - 1) * NH + h];
        float s = sc[j] * 0.125f + bia;
        if (last && ((t < 32) != (t2 < 32))) s -= 100.0f;
        sc[j] = s;
    }

    float mx = sc[0];
    #pragma unroll
    for (int j = 1; j < 16; j++) mx = fmaxf(mx, sc[j]);
    mx = fmaxf(mx, __shfl_xor_sync(0xffffffffu, mx, 1));
    mx = fmaxf(mx, __shfl_xor_sync(0xffffffffu, mx, 2));
    float sum = 0.0f;
    #pragma unroll
    for (int j = 0; j < 16; j++) { sc[j] = __expf(sc[j] - mx); sum += sc[j]; }
    sum += __shfl_xor_sync(0xffffffffu, sum, 1);
    sum += __shfl_xor_sync(0xffffffffu, sum, 2);
    float inv = 1.0f / sum;
    #pragma unroll
    for (int j = 0; j < 16; j++) sc[j] *= inv;

    if (write_attn) {
        size_t ao = ((((size_t)w * NH + h) * WSZ) + t) * WSZ + qd * 16;
        #pragma unroll
        for (int j4 = 0; j4 < 4; j4++) {
            float4 o4 = make_float4(sc[j4*4+0], sc[j4*4+1], sc[j4*4+2], sc[j4*4+3]);
            *(float4*)(attn_out + ao + j4 * 4) = o4;
        }
    }

    __syncthreads();
    #pragma unroll
    for (int j = 0; j < 16; j++)
        sQ[qd * 16 + j][t] = sc[j];
    __syncthreads();

    float oacc[16];
    #pragma unroll
    for (int j = 0; j < 16; j++) oacc[j] = 0.0f;
    #pragma unroll
    for (int t2 = 0; t2 < 64; t2++) {
        float sv = sQ[t2][t];
        #pragma unroll
        for (int j = 0; j < 16; j++)
            oacc[j] += sv * sV[t2][qd * 16 + j];
    }
    size_t co = base + (size_t)t * CC + qd * 16;
    #pragma unroll
    for (int j4 = 0; j4 < 4; j4++) {
        float4 o4 = make_float4(oacc[j4*4+0], oacc[j4*4+1], oacc[j4*4+2], oacc[j4*4+3]);
        *(float4*)(ctx + co + j4 * 4) = o4;
    }
}

// ---------------- depthwise conv along L (k=3, zero pad) + GELU --------------
__global__ void __launch_bounds__(256) dwconv_kernel(
    const float* __restrict__ f, const float* __restrict__ c2w,
    const float* __restrict__ c2b, float* __restrict__ out)
{
    size_t idx = (size_t)blockIdx.x * blockDim.x + threadIdx.x;
    if (idx >= (size_t)TOK * HID / 4) return;
    size_t e = idx * 4;
    int ch = (int)(e % HID);
    size_t row = e / HID;
    int l = (int)(row & (LL - 1));

    float4 fc = *(const float4*)(f + e);
    float4 fm = make_float4(0.f, 0.f, 0.f, 0.f);
    float4 fp = make_float4(0.f, 0.f, 0.f, 0.f);
    if (l > 0)      fm = *(const float4*)(f + e - HID);
    if (l < LL - 1) fp = *(const float4*)(f + e + HID);

    float r[4];
    float fmv[4] = {fm.x, fm.y, fm.z, fm.w};
    float fcv[4] = {fc.x, fc.y, fc.z, fc.w};
    float fpv[4] = {fp.x, fp.y, fp.z, fp.w};
    #pragma unroll
    for (int j = 0; j < 4; j++) {
        int c = ch + j;
        float w0 = c2w[c * 3 + 0], w1 = c2w[c * 3 + 1], w2 = c2w[c * 3 + 2];
        float dw = fmv[j] * w0 + fcv[j] * w1 + fpv[j] * w2 + c2b[c];
        r[j] = gelu_f(dw + fcv[j]);
    }
    *(float4*)(out + e) = make_float4(r[0], r[1], r[2], r[3]);
}

// ---------------- launch ------------------------------------------------------
extern "C" void kernel_launch(void* const* d_in, const int* in_sizes, int n_in,
                              void* d_out, int out_size)
{
    const float* x      = (const float*)d_in[0];
    const float* ln1_g  = (const float*)d_in[1];
    const float* ln1_b  = (const float*)d_in[2];
    const float* w_q    = (const float*)d_in[3];
    const float* w_k    = (const float*)d_in[4];
    const float* w_v    = (const float*)d_in[5];
    const float* w_o    = (const float*)d_in[6];
    const float* rel    = (const float*)d_in[7];
    const float* ln2_g  = (const float*)d_in[8];
    const float* ln2_b  = (const float*)d_in[9];
    const float* c1_w   = (const float*)d_in[10];
    const float* c1_b   = (const float*)d_in[11];
    const float* c2_w   = (const float*)d_in[12];
    const float* c2_b   = (const float*)d_in[13];
    const float* c3_w   = (const float*)d_in[14];
    const float* c3_b   = (const float*)d_in[15];
    float* out = (float*)d_out;

    float *h, *q, *k, *v, *ctx, *f, *f2;
    cudaGetSymbolAddress((void**)&h,   g_h);
    cudaGetSymbolAddress((void**)&q,   g_q);
    cudaGetSymbolAddress((void**)&k,   g_k);
    cudaGetSymbolAddress((void**)&v,   g_v);
    cudaGetSymbolAddress((void**)&ctx, g_ctx);
    cudaGetSymbolAddress((void**)&f,   g_f);
    cudaGetSymbolAddress((void**)&f2,  g_f2);
    float* y1  = q;
    float* fln = h;

    const int write_attn = ((size_t)out_size >= Y_ELEMS + ATTN_ELEMS) ? 1 : 0;
    float* attn_out = out + Y_ELEMS;

    // 1. LN1 + roll(-SHIFT)
    ln_kernel<<<TOK, 128>>>(x, h, ln1_g, ln1_b, 1);

    // 2. q/k/v projections (bf16x3 tensor-core)
    dim3 g512(CC / 128, TOK / 128);
    mma_gemm<0><<<g512, 256>>>(h, w_q, q, TOK, CC, CC, nullptr, nullptr);
    mma_gemm<0><<<g512, 256>>>(h, w_k, k, TOK, CC, CC, nullptr, nullptr);
    mma_gemm<0><<<g512, 256>>>(h, w_v, v, TOK, CC, CC, nullptr, nullptr);

    // 3. windowed attention
    dim3 ga(NH, BB * NW);
    attn_kernel<<<ga, 256>>>(q, k, v, rel, attn_out, ctx, write_attn);

    // 4. o-proj + roll(+SHIFT) + residual -> y1
    mma_gemm<1><<<g512, 256>>>(ctx, w_o, y1, TOK, CC, CC, nullptr, x);

    // 5. LN2
    ln_kernel<<<TOK, 128>>>(y1, fln, ln2_g, ln2_b, 0);

    // 6. c1 + bias + GELU
    dim3 g2048(HID / 128, TOK / 128);
    mma_gemm<2><<<g2048, 256>>>(fln, c1_w, f, TOK, HID, CC, c1_b, nullptr);

    // 7. depthwise conv (k=3) + bias + residual-in-FFN + GELU
    size_t nthread = (size_t)TOK * HID / 4;
    dwconv_kernel<<<(unsigned)((nthread + 255) / 256), 256>>>(f, c2_w, c2_b, f2);

    // 8. c3 + bias + residual -> final y
    mma_gemm<3><<<g512, 256>>>(f2, c3_w, out, TOK, CC, HID, c3_b, y1);
}

// round 4
// speedup vs baseline: 1.8277x; 1.0011x over previous
#include <cuda_runtime.h>
#include <cuda_bf16.h>
#include <math.h>
#include <stdint.h>

// Problem constants
#define BB   32
#define LL   4096
#define CC   512
#define WSZ  64
#define SHIFT 32
#define NH   8
#define DK   64
#define HID  2048
#define NW   64                 // windows per batch = LL/WS
#define TOK  (BB*LL)            // 131072 tokens
#define Y_ELEMS   ((size_t)TOK*CC)
#define ATTN_ELEMS ((size_t)BB*NW*NH*WSZ*WSZ)

// ---------------- scratch (device globals; no allocation allowed) -------------
__device__ float g_h  [(size_t)TOK*CC];
__device__ float g_q  [(size_t)TOK*CC];
__device__ float g_k  [(size_t)TOK*CC];
__device__ float g_v  [(size_t)TOK*CC];
__device__ float g_ctx[(size_t)TOK*CC];
__device__ float g_f  [(size_t)TOK*HID];
__device__ float g_f2 [(size_t)TOK*HID];

__device__ __forceinline__ float gelu_f(float x) {
    return 0.5f * x * (1.0f + erff(x * 0.70710678118654752440f));
}

// ---------------- LayerNorm (+ optional roll of source index) ----------------
__global__ void __launch_bounds__(128) ln_kernel(
    const float* __restrict__ x, float* __restrict__ out,
    const float* __restrict__ g, const float* __restrict__ b, int rolled)
{
    int row = blockIdx.x;
    int bt  = row >> 12;
    int l   = row & (LL - 1);
    int src = rolled ? ((bt << 12) | ((l + SHIFT) & (LL - 1))) : row;
    const float* xr = x + (size_t)src * CC;

    int t = threadIdx.x;
    float4 v = *(const float4*)(xr + t * 4);
    float s  = v.x + v.y + v.z + v.w;
    float ss = v.x*v.x + v.y*v.y + v.z*v.z + v.w*v.w;
    #pragma unroll
    for (int o = 16; o > 0; o >>= 1) {
        s  += __shfl_xor_sync(0xffffffffu, s,  o);
        ss += __shfl_xor_sync(0xffffffffu, ss, o);
    }
    __shared__ float red[8];
    int wid = t >> 5, lid = t & 31;
    if (lid == 0) { red[wid] = s; red[4 + wid] = ss; }
    __syncthreads();
    s  = red[0] + red[1] + red[2] + red[3];
    ss = red[4] + red[5] + red[6] + red[7];

    float mean = s * (1.0f / CC);
    float var  = ss * (1.0f / CC) - mean * mean;
    float rstd = rsqrtf(var + 1e-5f);

    float4 gg = *(const float4*)(g + t * 4);
    float4 bb4 = *(const float4*)(b + t * 4);
    float4 o4;
    o4.x = (v.x - mean) * rstd * gg.x + bb4.x;
    o4.y = (v.y - mean) * rstd * gg.y + bb4.y;
    o4.z = (v.z - mean) * rstd * gg.z + bb4.z;
    o4.w = (v.w - mean) * rstd * gg.w + bb4.w;
    *(float4*)(out + (size_t)row * CC + t * 4) = o4;
}

// ---------------- bf16x3 split-precision tensor-core GEMM --------------------
// C[M,N] = A[M,K] @ B[N,K]^T  with fp32-equivalent accuracy:
//   x = hi(x) + lo(x) in bf16;  acc += Ah*Bh + Ah*Bl + Al*Bh   (fp32 accum)
// MODE 0: plain   MODE 1: roll(+SHIFT) dest + residual
// MODE 2: +bias, GELU    MODE 3: +bias + addsrc
#define Bb16M 128
#define Bb16N 128
#define Bb16K 32

__device__ __forceinline__ uint32_t cvta_smem(const void* p) {
    return (uint32_t)__cvta_generic_to_shared(p);
}
__device__ __forceinline__ void ldsm4(uint32_t* r, uint32_t addr) {
    asm volatile("ldmatrix.sync.aligned.m8n8.x4.shared.b16 {%0,%1,%2,%3}, [%4];"
        : "=r"(r[0]), "=r"(r[1]), "=r"(r[2]), "=r"(r[3]) : "r"(addr));
}
__device__ __forceinline__ void ldsm2(uint32_t* r, uint32_t addr) {
    asm volatile("ldmatrix.sync.aligned.m8n8.x2.shared.b16 {%0,%1}, [%2];"
        : "=r"(r[0]), "=r"(r[1]) : "r"(addr));
}
__device__ __forceinline__ void mma16816(float* c, const uint32_t* a, const uint32_t* b) {
    asm volatile("mma.sync.aligned.m16n8k16.row.col.f32.bf16.bf16.f32 "
        "{%0,%1,%2,%3},{%4,%5,%6,%7},{%8,%9},{%0,%1,%2,%3};"
        : "+f"(c[0]), "+f"(c[1]), "+f"(c[2]), "+f"(c[3])
        : "r"(a[0]), "r"(a[1]), "r"(a[2]), "r"(a[3]), "r"(b[0]), "r"(b[1]));
}
// swizzled element offset within a [rows][32] bf16 tile (conflict-free ldmatrix)
__device__ __forceinline__ int swz(int r, int k) {
    return r * 32 + ((((k >> 3) ^ ((r >> 1) & 3)) & 3) << 3) + (k & 7);
}
__device__ __forceinline__ uint32_t pack_bf2(__nv_bfloat16 a, __nv_bfloat16 b) {
    return (uint32_t)__bfloat16_as_ushort(a) | ((uint32_t)__bfloat16_as_ushort(b) << 16);
}
__device__ __forceinline__ void split_store4(
    __nv_bfloat16* Hh, __nv_bfloat16* Ll, int off, float4 v)
{
    __nv_bfloat16 h0 = __float2bfloat16(v.x);
    __nv_bfloat16 h1 = __float2bfloat16(v.y);
    __nv_bfloat16 h2 = __float2bfloat16(v.z);
    __nv_bfloat16 h3 = __float2bfloat16(v.w);
    __nv_bfloat16 l0 = __float2bfloat16(v.x - __bfloat162float(h0));
    __nv_bfloat16 l1 = __float2bfloat16(v.y - __bfloat162float(h1));
    __nv_bfloat16 l2 = __float2bfloat16(v.z - __bfloat162float(h2));
    __nv_bfloat16 l3 = __float2bfloat16(v.w - __bfloat162float(h3));
    *(uint2*)(Hh + off) = make_uint2(pack_bf2(h0, h1), pack_bf2(h2, h3));
    *(uint2*)(Ll + off) = make_uint2(pack_bf2(l0, l1), pack_bf2(l2, l3));
}

template<int MODE>
__global__ void __launch_bounds__(256) mma_gemm(
    const float* __restrict__ A, const float* __restrict__ Bw,
    float* __restrict__ Cc, int M, int N, int K,
    const float* __restrict__ bias, const float* __restrict__ addsrc)
{
    __shared__ __nv_bfloat16 Ah[Bb16M * Bb16K];
    __shared__ __nv_bfloat16 Al[Bb16M * Bb16K];
    __shared__ __nv_bfloat16 Bh[Bb16N * Bb16K];
    __shared__ __nv_bfloat16 Bl[Bb16N * Bb16K];

    const int tid  = threadIdx.x;
    const int bm   = blockIdx.y * Bb16M;
    const int bn   = blockIdx.x * Bb16N;
    const int warp = tid >> 5, lane = tid & 31;
    const int wm = (warp & 1) * 64;      // 2 warps along M
    const int wn = (warp >> 1) * 32;     // 4 warps along N

    float acc[4][4][4];
    #pragma unroll
    for (int i = 0; i < 4; i++)
        #pragma unroll
        for (int j = 0; j < 4; j++)
            #pragma unroll
            for (int c = 0; c < 4; c++) acc[i][j][c] = 0.0f;

    // gmem tile loads: 128 rows x 32 cols fp32 each for A and B
    const int lr = tid >> 3;          // 0..31
    const int lc = (tid & 7) * 4;     // 0,4,...,28
    const float* Aptr = A  + (size_t)(bm + lr) * K + lc;
    const float* Bptr = Bw + (size_t)(bn + lr) * K + lc;

    float4 ra[4], rb[4];
    #pragma unroll
    for (int i = 0; i < 4; i++) {
        ra[i] = *(const float4*)(Aptr + (size_t)i * 32 * K);
        rb[i] = *(const float4*)(Bptr + (size_t)i * 32 * K);
    }

    const int nk = K / Bb16K;
    for (int kb = 0; kb < nk; kb++) {
        #pragma unroll
        for (int i = 0; i < 4; i++) {
            int r = lr + i * 32;
            int off = swz(r, lc);
            split_store4(Ah, Al, off, ra[i]);
            split_store4(Bh, Bl, off, rb[i]);
        }
        __syncthreads();

        if (kb + 1 < nk) {
            size_t ko = (size_t)(kb + 1) * Bb16K;
            #pragma unroll
            for (int i = 0; i < 4; i++) {
                ra[i] = *(const float4*)(Aptr + ko + (size_t)i * 32 * K);
                rb[i] = *(const float4*)(Bptr + ko + (size_t)i * 32 * K);
            }
        }

        #pragma unroll
        for (int kf = 0; kf < 2; kf++) {
            const int k0 = kf * 16;
            uint32_t fah[4][4], fal[4][4], fbh[4][2], fbl[4][2];

            const int arow = wm + (lane & 15);
            const int akc  = k0 + (lane >> 4) * 8;
            #pragma unroll
            for (int mi = 0; mi < 4; mi++) {
                int off = swz(arow + mi * 16, akc);
                ldsm4(fah[mi], cvta_smem(Ah + off));
                ldsm4(fal[mi], cvta_smem(Al + off));
            }
            const int brow = wn + (lane & 7);
            const int bkc  = k0 + ((lane >> 3) & 1) * 8;
            #pragma unroll
            for (int ni = 0; ni < 4; ni++) {
                int off = swz(brow + ni * 8, bkc);
                ldsm2(fbh[ni], cvta_smem(Bh + off));
                ldsm2(fbl[ni], cvta_smem(Bl + off));
            }
            #pragma unroll
            for (int mi = 0; mi < 4; mi++)
                #pragma unroll
                for (int ni = 0; ni < 4; ni++) {
                    mma16816(acc[mi][ni], fah[mi], fbh[ni]);
                    mma16816(acc[mi][ni], fah[mi], fbl[ni]);
                    mma16816(acc[mi][ni], fal[mi], fbh[ni]);
                }
        }
        __syncthreads();
    }

    // epilogue: thread owns (row = base + lane/4 [+8], cols = (lane%4)*2, +1)
    const int rbase = bm + wm + (lane >> 2);
    const int cbase = bn + wn + (lane & 3) * 2;
    #pragma unroll
    for (int mi = 0; mi < 4; mi++) {
        #pragma unroll
        for (int half = 0; half < 2; half++) {
            int m = rbase + mi * 16 + half * 8;
            #pragma unroll
            for (int ni = 0; ni < 4; ni++) {
                int n = cbase + ni * 8;
                float v0 = acc[mi][ni][half * 2 + 0];
                float v1 = acc[mi][ni][half * 2 + 1];
                if (MODE == 0) {
                    *(float2*)(Cc + (size_t)m * N + n) = make_float2(v0, v1);
                } else if (MODE == 1) {
                    int bt = m >> 12, l = m & (LL - 1);
                    int ld = (l + SHIFT) & (LL - 1);
                    size_t mrow = ((size_t)(bt << 12) | ld);
                    float2 r0 = *(const float2*)(addsrc + mrow * N + n);
                    *(float2*)(Cc + mrow * N + n) = make_float2(v0 + r0.x, v1 + r0.y);
                } else if (MODE == 2) {
                    float2 b2 = *(const float2*)(bias + n);
                    *(float2*)(Cc + (size_t)m * N + n) =
                        make_float2(gelu_f(v0 + b2.x), gelu_f(v1 + b2.y));
                } else {
                    float2 b2 = *(const float2*)(bias + n);
                    float2 r0 = *(const float2*)(addsrc + (size_t)m * N + n);
                    *(float2*)(Cc + (size_t)m * N + n) =
                        make_float2(v0 + b2.x + r0.x, v1 + b2.y + r0.y);
                }
            }
        }
    }
}

// ---------------- window attention (fp32 SIMT; small) ------------------------
__global__ void __launch_bounds__(256) attn_kernel(
    const float* __restrict__ q, const float* __restrict__ k, const float* __restrict__ v,
    const float* __restrict__ rel_table,
    float* __restrict__ attn_out, float* __restrict__ ctx, int write_attn)
{
    __shared__ float sQ[64][64];
    __shared__ float sK[64][64];
    __shared__ float sV[64][64];

    const int h = blockIdx.x;
    const int w = blockIdx.y;
    const int tid = threadIdx.x;
    const int t  = tid >> 2;
    const int qd = tid & 3;

    const size_t base = (size_t)w * WSZ * CC + (size_t)h * DK;

    #pragma unroll
    for (int i = 0; i < 4; i++) {
        int d0 = qd * 16 + i * 4;
        float4 qv = *(const float4*)(q + base + (size_t)t * CC + d0);
        sQ[d0 + 0][t] = qv.x; sQ[d0 + 1][t] = qv.y;
        sQ[d0 + 2][t] = qv.z; sQ[d0 + 3][t] = qv.w;
        float4 kv = *(const float4*)(k + base + (size_t)t * CC + d0);
        sK[d0 + 0][t] = kv.x; sK[d0 + 1][t] = kv.y;
        sK[d0 + 2][t] = kv.z; sK[d0 + 3][t] = kv.w;
        float4 vv = *(const float4*)(v + base + (size_t)t * CC + d0);
        *(float4*)(&sV[t][d0]) = vv;
    }
    __syncthreads();

    float sc[16];
    #pragma unroll
    for (int j = 0; j < 16; j++) sc[j] = 0.0f;
    #pragma unroll
    for (int d = 0; d < 64; d++) {
        float qv = sQ[d][t];
        #pragma unroll
        for (int j = 0; j < 16; j++)
            sc[j] += qv * sK[d][qd * 16 + j];
    }

    const bool last = ((w & (NW - 1)) == (NW - 1));
    #pragma unroll
    for (int j = 0; j < 16; j++) {
        int t2 = qd * 16 + j;
        float bia = rel_table[(t - t2 + WSZ - 1) * NH + h];
        float s = sc[j] * 0.125f + bia;
        if (last && ((t < 32) != (t2 < 32))) s -= 100.0f;
        sc[j] = s;
    }

    float mx = sc[0];
    #pragma unroll
    for (int j = 1; j < 16; j++) mx = fmaxf(mx, sc[j]);
    mx = fmaxf(mx, __shfl_xor_sync(0xffffffffu, mx, 1));
    mx = fmaxf(mx, __shfl_xor_sync(0xffffffffu, mx, 2));
    float sum = 0.0f;
    #pragma unroll
    for (int j = 0; j < 16; j++) { sc[j] = __expf(sc[j] - mx); sum += sc[j]; }
    sum += __shfl_xor_sync(0xffffffffu, sum, 1);
    sum += __shfl_xor_sync(0xffffffffu, sum, 2);
    float inv = 1.0f / sum;
    #pragma unroll
    for (int j = 0; j < 16; j++) sc[j] *= inv;

    if (write_attn) {
        size_t ao = ((((size_t)w * NH + h) * WSZ) + t) * WSZ + qd * 16;
        #pragma unroll
        for (int j4 = 0; j4 < 4; j4++) {
            float4 o4 = make_float4(sc[j4*4+0], sc[j4*4+1], sc[j4*4+2], sc[j4*4+3]);
            *(float4*)(attn_out + ao + j4 * 4) = o4;
        }
    }

    __syncthreads();
    #pragma unroll
    for (int j = 0; j < 16; j++)
        sQ[qd * 16 + j][t] = sc[j];
    __syncthreads();

    float oacc[16];
    #pragma unroll
    for (int j = 0; j < 16; j++) oacc[j] = 0.0f;
    #pragma unroll
    for (int t2 = 0; t2 < 64; t2++) {
        float sv = sQ[t2][t];
        #pragma unroll
        for (int j = 0; j < 16; j++)
            oacc[j] += sv * sV[t2][qd * 16 + j];
    }
    size_t co = base + (size_t)t * CC + qd * 16;
    #pragma unroll
    for (int j4 = 0; j4 < 4; j4++) {
        float4 o4 = make_float4(oacc[j4*4+0], oacc[j4*4+1], oacc[j4*4+2], oacc[j4*4+3]);
        *(float4*)(ctx + co + j4 * 4) = o4;
    }
}

// ---------------- depthwise conv along L (k=3, zero pad) + GELU --------------
__global__ void __launch_bounds__(256) dwconv_kernel(
    const float* __restrict__ f, const float* __restrict__ c2w,
    const float* __restrict__ c2b, float* __restrict__ out)
{
    size_t idx = (size_t)blockIdx.x * blockDim.x + threadIdx.x;
    if (idx >= (size_t)TOK * HID / 4) return;
    size_t e = idx * 4;
    int ch = (int)(e % HID);
    size_t row = e / HID;
    int l = (int)(row & (LL - 1));

    float4 fc = *(const float4*)(f + e);
    float4 fm = make_float4(0.f, 0.f, 0.f, 0.f);
    float4 fp = make_float4(0.f, 0.f, 0.f, 0.f);
    if (l > 0)      fm = *(const float4*)(f + e - HID);
    if (l < LL - 1) fp = *(const float4*)(f + e + HID);

    float r[4];
    float fmv[4] = {fm.x, fm.y, fm.z, fm.w};
    float fcv[4] = {fc.x, fc.y, fc.z, fc.w};
    float fpv[4] = {fp.x, fp.y, fp.z, fp.w};
    #pragma unroll
    for (int j = 0; j < 4; j++) {
        int c = ch + j;
        float w0 = c2w[c * 3 + 0], w1 = c2w[c * 3 + 1], w2 = c2w[c * 3 + 2];
        float dw = fmv[j] * w0 + fcv[j] * w1 + fpv[j] * w2 + c2b[c];
        r[j] = gelu_f(dw + fcv[j]);
    }
    *(float4*)(out + e) = make_float4(r[0], r[1], r[2], r[3]);
}

// ---------------- launch ------------------------------------------------------
extern "C" void kernel_launch(void* const* d_in, const int* in_sizes, int n_in,
                              void* d_out, int out_size)
{
    const float* x      = (const float*)d_in[0];
    const float* ln1_g  = (const float*)d_in[1];
    const float* ln1_b  = (const float*)d_in[2];
    const float* w_q    = (const float*)d_in[3];
    const float* w_k    = (const float*)d_in[4];
    const float* w_v    = (const float*)d_in[5];
    const float* w_o    = (const float*)d_in[6];
    const float* rel    = (const float*)d_in[7];
    const float* ln2_g  = (const float*)d_in[8];
    const float* ln2_b  = (const float*)d_in[9];
    const float* c1_w   = (const float*)d_in[10];
    const float* c1_b   = (const float*)d_in[11];
    const float* c2_w   = (const float*)d_in[12];
    const float* c2_b   = (const float*)d_in[13];
    const float* c3_w   = (const float*)d_in[14];
    const float* c3_b   = (const float*)d_in[15];
    float* out = (float*)d_out;

    float *h, *q, *k, *v, *ctx, *f, *f2;
    cudaGetSymbolAddress((void**)&h,   g_h);
    cudaGetSymbolAddress((void**)&q,   g_q);
    cudaGetSymbolAddress((void**)&k,   g_k);
    cudaGetSymbolAddress((void**)&v,   g_v);
    cudaGetSymbolAddress((void**)&ctx, g_ctx);
    cudaGetSymbolAddress((void**)&f,   g_f);
    cudaGetSymbolAddress((void**)&f2,  g_f2);
    float* y1  = q;
    float* fln = h;

    const int write_attn = ((size_t)out_size >= Y_ELEMS + ATTN_ELEMS) ? 1 : 0;
    float* attn_out = out + Y_ELEMS;

    // 1. LN1 + roll(-SHIFT)
    ln_kernel<<<TOK, 128>>>(x, h, ln1_g, ln1_b, 1);

    // 2. q/k/v projections (bf16x3 tensor-core)
    dim3 g512(CC / 128, TOK / 128);
    mma_gemm<0><<<g512, 256>>>(h, w_q, q, TOK, CC, CC, nullptr, nullptr);
    mma_gemm<0><<<g512, 256>>>(h, w_k, k, TOK, CC, CC, nullptr, nullptr);
    mma_gemm<0><<<g512, 256>>>(h, w_v, v, TOK, CC, CC, nullptr, nullptr);

    // 3. windowed attention
    dim3 ga(NH, BB * NW);
    attn_kernel<<<ga, 256>>>(q, k, v, rel, attn_out, ctx, write_attn);

    // 4. o-proj + roll(+SHIFT) + residual -> y1
    mma_gemm<1><<<g512, 256>>>(ctx, w_o, y1, TOK, CC, CC, nullptr, x);

    // 5. LN2
    ln_kernel<<<TOK, 128>>>(y1, fln, ln2_g, ln2_b, 0);

    // 6. c1 + bias + GELU
    dim3 g2048(HID / 128, TOK / 128);
    mma_gemm<2><<<g2048, 256>>>(fln, c1_w, f, TOK, HID, CC, c1_b, nullptr);

    // 7. depthwise conv (k=3) + bias + residual-in-FFN + GELU
    size_t nthread = (size_t)TOK * HID / 4;
    dwconv_kernel<<<(unsigned)((nthread + 255) / 256), 256>>>(f, c2_w, c2_b, f2);

    // 8. c3 + bias + residual -> final y
    mma_gemm<3><<<g512, 256>>>(f2, c3_w, out, TOK, CC, HID, c3_b, y1);
}